// round 15
// baseline (speedup 1.0000x reference)
#include <cuda_runtime.h>
#include <cuda_fp16.h>
#include <cstdint>
#include <math.h>

typedef __half f16;

#define NTOK 8192
#define DDIM 2048
#define KDIM 2048
#define SCALING_F (16.0f / 2048.0f)
#define EPS_F 1e-12f

// ---------------------------------------------------------------------------
// Static device scratch
// ---------------------------------------------------------------------------
__device__ f16 g_x16[(size_t)NTOK * DDIM];     // x
__device__ f16 g_lA [(size_t)DDIM * DDIM];     // lora_A
__device__ f16 g_lB [(size_t)DDIM * DDIM];     // lora_B
__device__ f16 g_ds [(size_t)DDIM * DDIM];     // cs ⊙ direction
__device__ f16 g_T1 [(size_t)DDIM * DDIM];     // T1 = (cs⊙dir) @ lora_A^T
__device__ f16 g_QT [(size_t)DDIM * DDIM];     // QT = T1 @ lora_B^T
__device__ float g_cs[DDIM];

// ---------------------------------------------------------------------------
// PTX helpers — standard sm_80 features only
// ---------------------------------------------------------------------------
__device__ __forceinline__ uint32_t smem_u32(const void* p) {
    uint32_t a;
    asm("{ .reg .u64 t; cvta.to.shared.u64 t, %1; cvt.u32.u64 %0, t; }" : "=r"(a) : "l"(p));
    return a;
}
__device__ __forceinline__ void cp_async16(uint32_t dst, const void* src) {
    asm volatile("cp.async.cg.shared.global [%0], [%1], 16;" :: "r"(dst), "l"(src));
}
__device__ __forceinline__ void cp_commit() { asm volatile("cp.async.commit_group;" ::: "memory"); }
template <int N>
__device__ __forceinline__ void cp_wait() { asm volatile("cp.async.wait_group %0;" :: "n"(N) : "memory"); }

#define LDSM_X4(r0, r1, r2, r3, addr) \
    asm volatile("ldmatrix.sync.aligned.m8n8.x4.shared.b16 {%0,%1,%2,%3}, [%4];" \
        : "=r"(r0), "=r"(r1), "=r"(r2), "=r"(r3) : "r"(addr))

__device__ __forceinline__ void mma_f16(float* c, const uint32_t* a, const uint32_t* b) {
    asm volatile(
        "mma.sync.aligned.m16n8k16.row.col.f32.f16.f16.f32 "
        "{%0,%1,%2,%3}, {%4,%5,%6,%7}, {%8,%9}, {%0,%1,%2,%3};"
        : "+f"(c[0]), "+f"(c[1]), "+f"(c[2]), "+f"(c[3])
        : "r"(a[0]), "r"(a[1]), "r"(a[2]), "r"(a[3]), "r"(b[0]), "r"(b[1]));
}

// ---------------------------------------------------------------------------
// Conversion primitive: 8 fp32 -> 8 fp16, 16B store
// ---------------------------------------------------------------------------
__device__ __forceinline__ void cvt8(const float* __restrict__ in, f16* __restrict__ out,
                                     int i, float s) {
    float4 a = ((const float4*)in)[i * 2];
    float4 b = ((const float4*)in)[i * 2 + 1];
    __half2 h0 = __floats2half2_rn(a.x * s, a.y * s);
    __half2 h1 = __floats2half2_rn(a.z * s, a.w * s);
    __half2 h2 = __floats2half2_rn(b.x * s, b.y * s);
    __half2 h3 = __floats2half2_rn(b.z * s, b.w * s);
    uint4 v; v.x = *(uint32_t*)&h0; v.y = *(uint32_t*)&h1;
    v.z = *(uint32_t*)&h2; v.w = *(uint32_t*)&h3;
    ((uint4*)out)[i] = v;
}

// ---------------------------------------------------------------------------
// Prep 1: cs[o] = ||magnitude|| * SCALING / max(||direction[o,:]||, eps)
// ---------------------------------------------------------------------------
__global__ void magcol_kernel(const float* __restrict__ magnitude,
                              const float* __restrict__ direction) {
    int o = blockIdx.x;
    const float* row = direction + (size_t)o * DDIM;
    float sm = 0.0f, sd = 0.0f;
    for (int i = threadIdx.x; i < DDIM; i += 256) {
        float a = magnitude[i];  sm += a * a;
        float b = row[i];        sd += b * b;
    }
    __shared__ float rm[256], rd[256];
    rm[threadIdx.x] = sm; rd[threadIdx.x] = sd;
    __syncthreads();
    for (int off = 128; off > 0; off >>= 1) {
        if (threadIdx.x < off) {
            rm[threadIdx.x] += rm[threadIdx.x + off];
            rd[threadIdx.x] += rd[threadIdx.x + off];
        }
        __syncthreads();
    }
    if (threadIdx.x == 0)
        g_cs[o] = sqrtf(rm[0]) * SCALING_F / fmaxf(sqrtf(rd[0]), EPS_F);
}

// ---------------------------------------------------------------------------
// Prep 2: weight conversions only (lora_A, lora_B, cs⊙dir); x handled by
// idle CTAs inside gemm1/gemm2.
// ---------------------------------------------------------------------------
#define NX8 ((NTOK * DDIM) / 8)
#define ND8 ((DDIM * DDIM) / 8)
#define XU  (NX8 / 256)            // 8192 x-units (256 threads x 8 elems each)
#define BD  (ND8 / 256)            // 2048 blocks per weight tensor

__global__ void weights_prep(const float* __restrict__ lA,
                             const float* __restrict__ lB,
                             const float* __restrict__ dir) {
    int b = blockIdx.x;
    if (b < BD) {
        cvt8(lA, g_lA, b * 256 + threadIdx.x, 1.0f);
    } else if (b < 2 * BD) {
        cvt8(lB, g_lB, (b - BD) * 256 + threadIdx.x, 1.0f);
    } else {
        int i = (b - 2 * BD) * 256 + threadIdx.x;
        int row = (i * 8) / DDIM;        // 8 | DDIM -> row constant across the 8
        cvt8(dir, g_ds, i, g_cs[row]);
    }
}

// Fallback x conversion (used only if grid <= tiles, i.e. no idle CTAs)
__global__ void x_prep(const float* __restrict__ x) {
    cvt8(x, g_x16, blockIdx.x * 256 + threadIdx.x, 1.0f);
}

// ---------------------------------------------------------------------------
// PERSISTENT fp16 GEMM (single pass): C = A[M,K] * B[N,K]^T, K = 2048.
// CTA tile 128x256, warp tile 64x64, BK=64, S=3 stages (48 KB each).
// grid = #SMs; tiles walked stride-grid; cp.async pipeline continues across
// tiles. CTAs with blockIdx >= #tiles run the x fp32->fp16 conversion side
// job (units [xBase, xBase+xUnits) split among them) — hides x prep under
// the small GEMMs. EPI=0: fp32 out. EPI=1: fp16 out.
// ---------------------------------------------------------------------------
template <int EPI>
__global__ __launch_bounds__(256, 1)
void gemm_f16(const f16* __restrict__ A_g, const f16* __restrict__ B_g,
              float* __restrict__ Cf, f16* __restrict__ Ch,
              int tilesM, int tilesN,
              const float* __restrict__ xsrc, int xBase, int xUnits)
{
    extern __shared__ __align__(128) char smem[];
    const uint32_t sb = smem_u32(smem);

    constexpr int K = KDIM, BK = 64, NC = K / BK, S = 3;
    constexpr uint32_t TA = 128 * 128;       // 16 KB
    constexpr uint32_t TB = 256 * 128;       // 32 KB
    constexpr uint32_t STAGE = TA + TB;      // 48 KB

    const int T = tilesM * tilesN;
    const int tid = threadIdx.x;

    int tile = blockIdx.x;
    if (tile >= T) {
        // ---------- side job: x fp32 -> fp16 conversion ----------
        if (xUnits > 0) {
            const int idle = gridDim.x - T;
            for (int u = xBase + (tile - T); u < xBase + xUnits; u += idle)
                cvt8(xsrc, g_x16, u * 256 + tid, 1.0f);
        }
        return;
    }

    const int ldc = tilesN * 256;
    const int wid = tid >> 5, lane = tid & 31;
    const int wm = (wid >> 2) * 64;
    const int wn = (wid & 3) * 64;

    const int lrow = tid >> 3;
    const int lg   = tid & 7;

    const int a_row_l = lane & 15;
    const int a_kb_l  = (lane >> 4) * 16;
    const int b_n_l   = (lane & 7) + ((lane >> 4) << 3);
    const int b_kb_l  = ((lane >> 3) & 1) * 16;

    int tm = tile / tilesN, tn = tile - tm * tilesN;
    const f16* cA = A_g + (size_t)tm * 128 * K;
    const f16* cB = B_g + (size_t)tn * 256 * K;

    auto load_stage = [&](int slot, const f16* pA, const f16* pB, int k0) {
        const uint32_t base = sb + (uint32_t)slot * STAGE;
        const int ks = k0 + lg * 8;
        #pragma unroll
        for (int j = 0; j < 4; j++) {          // A: 128 rows
            const int row = lrow + 32 * j;
            uint32_t off = (uint32_t)row * 128 + (uint32_t)lg * 16;
            off ^= ((uint32_t)row & 7) << 4;
            cp_async16(base + off, pA + (size_t)row * K + ks);
        }
        #pragma unroll
        for (int j = 0; j < 8; j++) {          // B: 256 rows
            const int row = lrow + 32 * j;
            uint32_t off = (uint32_t)row * 128 + (uint32_t)lg * 16;
            off ^= ((uint32_t)row & 7) << 4;
            cp_async16(base + TA + off, pB + (size_t)row * K + ks);
        }
        cp_commit();
    };

    load_stage(0, cA, cB, 0);
    load_stage(1, cA, cB, BK);
    int scur = 0, sld = 2;   // consume slot / next load slot (rotate mod S)

    uint32_t ah[2][4][4], bh[2][8][2];

    while (true) {
        const int ntile = tile + gridDim.x;
        const bool have_next = ntile < T;
        const f16 *nA = cA, *nB = cB;
        int nm = tm, nn = tn;
        if (have_next) {
            nm = ntile / tilesN; nn = ntile - nm * tilesN;
            nA = A_g + (size_t)nm * 128 * K;
            nB = B_g + (size_t)nn * 256 * K;
        }

        float acc[4][8][4];
        #pragma unroll
        for (int a = 0; a < 4; a++)
            #pragma unroll
            for (int b = 0; b < 8; b++)
                #pragma unroll
                for (int q = 0; q < 4; q++) acc[a][b][q] = 0.0f;

        for (int c = 0; c < NC; c++) {
            if (c == NC - 1 && !have_next) cp_wait<0>(); else cp_wait<1>();
            __syncthreads();

            if (c + 2 < NC)            load_stage(sld, cA, cB, (c + 2) * BK);
            else if (have_next)        load_stage(sld, nA, nB, (c + 2 - NC) * BK);

            const uint32_t stg = sb + (uint32_t)scur * STAGE;
            const uint32_t As = stg, Bs = stg + TA;

            auto frags = [&](int buf, int s) {
                const int kb = s * 32;
                #pragma unroll
                for (int mi = 0; mi < 4; mi++) {
                    const int row = wm + mi * 16 + a_row_l;
                    const uint32_t off = (uint32_t)row * 128
                        + (((uint32_t)(kb + a_kb_l)) ^ (((uint32_t)row & 7) << 4));
                    LDSM_X4(ah[buf][mi][0], ah[buf][mi][1], ah[buf][mi][2], ah[buf][mi][3],
                            As + off);
                }
                #pragma unroll
                for (int nj2 = 0; nj2 < 4; nj2++) {
                    const int nr = wn + nj2 * 16 + b_n_l;
                    const uint32_t off = (uint32_t)nr * 128
                        + (((uint32_t)(kb + b_kb_l)) ^ (((uint32_t)nr & 7) << 4));
                    LDSM_X4(bh[buf][2*nj2][0], bh[buf][2*nj2][1],
                            bh[buf][2*nj2+1][0], bh[buf][2*nj2+1][1], Bs + off);
                }
            };

            frags(0, 0);
            #pragma unroll
            for (int s = 0; s < 4; s++) {
                const int cur = s & 1;
                if (s < 3) frags(cur ^ 1, s + 1);
                #pragma unroll
                for (int mi = 0; mi < 4; mi++)
                    #pragma unroll
                    for (int nj = 0; nj < 8; nj++)
                        mma_f16(acc[mi][nj], ah[cur][mi], bh[cur][nj]);
            }

            if (++scur == S) scur = 0;
            if (++sld == S) sld = 0;
        }

        // ---------------- epilogue (overlaps next tile's loads) ----------
        const int m0 = tm * 128, n0 = tn * 256;
        const int g  = lane >> 2;
        const int t4 = lane & 3;
        #pragma unroll
        for (int mi = 0; mi < 4; mi++) {
            const int r0 = m0 + wm + mi * 16 + g;
            const int r1 = r0 + 8;
            #pragma unroll
            for (int nj = 0; nj < 8; nj++) {
                const int col = n0 + wn + nj * 8 + t4 * 2;
                float c0 = acc[mi][nj][0], c1 = acc[mi][nj][1];
                float c2 = acc[mi][nj][2], c3 = acc[mi][nj][3];
                if (EPI == 0) {
                    float2 v0; v0.x = c0; v0.y = c1;
                    float2 v1; v1.x = c2; v1.y = c3;
                    *(float2*)(Cf + (size_t)r0 * ldc + col) = v0;
                    *(float2*)(Cf + (size_t)r1 * ldc + col) = v1;
                } else {
                    __half2 h0 = __floats2half2_rn(c0, c1);
                    __half2 h1 = __floats2half2_rn(c2, c3);
                    *(__half2*)(Ch + (size_t)r0 * ldc + col) = h0;
                    *(__half2*)(Ch + (size_t)r1 * ldc + col) = h1;
                }
            }
        }

        if (!have_next) break;
        tile = ntile; tm = nm; tn = nn; cA = nA; cB = nB;
    }
}

// ---------------------------------------------------------------------------
// Launch: magcol(1) -> weights_prep(2) -> gemm1(+x lo half)(3)
//         -> gemm2(+x hi half)(4) -> gemm3(5)
// Chain:  T1 = (cs⊙dir) @ lora_A^T ;  QT = T1 @ lora_B^T ;  out = x @ QT^T
// ---------------------------------------------------------------------------
extern "C" void kernel_launch(void* const* d_in, const int* in_sizes, int n_in,
                              void* d_out, int out_size) {
    const float* x         = (const float*)d_in[0];
    const float* lora_A    = (const float*)d_in[1];
    const float* lora_B    = (const float*)d_in[2];
    const float* magnitude = (const float*)d_in[3];
    const float* direction = (const float*)d_in[4];
    float* out = (float*)d_out;

    f16 *x16, *lA, *lB, *ds, *T1, *QT;
    cudaGetSymbolAddress((void**)&x16, g_x16);
    cudaGetSymbolAddress((void**)&lA, g_lA);
    cudaGetSymbolAddress((void**)&lB, g_lB);
    cudaGetSymbolAddress((void**)&ds, g_ds);
    cudaGetSymbolAddress((void**)&T1, g_T1);
    cudaGetSymbolAddress((void**)&QT, g_QT);

    constexpr int SM = 3 * (128 * 128 + 256 * 128);   // 147456 bytes
    cudaFuncSetAttribute(gemm_f16<0>, cudaFuncAttributeMaxDynamicSharedMemorySize, SM);
    cudaFuncSetAttribute(gemm_f16<1>, cudaFuncAttributeMaxDynamicSharedMemorySize, SM);

    int nsm = 148;
    cudaDeviceGetAttribute(&nsm, cudaDevAttrMultiProcessorCount, 0);

    const int tsN = DDIM / 256;            // 8
    const int tsM_s = DDIM / 128;          // 16  -> 128 tiles (small GEMMs)
    const int tsM_b = NTOK / 128;          // 64  -> 512 tiles (big GEMM)
    const int Tsmall = tsM_s * tsN;        // 128

    const bool idle_ok = nsm > Tsmall;     // idle CTAs exist in small GEMMs

    // 1: norms (must precede prep: dir is pre-scaled by cs)
    magcol_kernel<<<DDIM, 256>>>(magnitude, direction);
    // 2: weight conversions (x handled by gemm1/gemm2 idle CTAs)
    weights_prep<<<3 * BD, 256>>>(lora_A, lora_B, direction);
    if (!idle_ok)
        x_prep<<<XU, 256>>>(x);

    const int xu1 = idle_ok ? XU / 2 : 0;
    const int xu2 = idle_ok ? XU - XU / 2 : 0;

    // 3: T1 = (cs⊙dir) @ lora_A^T   (fp16 out; idle CTAs convert x[0, XU/2))
    gemm_f16<1><<<nsm, 256, SM>>>(ds, lA, nullptr, T1, tsM_s, tsN, x, 0, xu1);
    // 4: QT = T1 @ lora_B^T          (fp16 out; idle CTAs convert x[XU/2, XU))
    gemm_f16<1><<<nsm, 256, SM>>>(T1, lB, nullptr, QT, tsM_s, tsN, x, XU / 2, xu2);
    // 5: out = x @ QT^T              (fp32 out; persistent walk of 512 tiles)
    gemm_f16<0><<<nsm, 256, SM>>>(x16, QT, out, nullptr, tsM_b, tsN, nullptr, 0, 0);
}

// round 16
// speedup vs baseline: 1.3372x; 1.3372x over previous
#include <cuda_runtime.h>
#include <cuda_fp16.h>
#include <cstdint>
#include <math.h>

typedef __half f16;

#define NTOK 8192
#define DDIM 2048
#define KDIM 2048
#define SCALING_F (16.0f / 2048.0f)
#define EPS_F 1e-12f

// ---------------------------------------------------------------------------
// Static device scratch
// ---------------------------------------------------------------------------
__device__ f16 g_x16[(size_t)NTOK * DDIM];     // x
__device__ f16 g_lA [(size_t)DDIM * DDIM];     // lora_A
__device__ f16 g_lB [(size_t)DDIM * DDIM];     // lora_B
__device__ f16 g_ds [(size_t)DDIM * DDIM];     // cs ⊙ direction
__device__ f16 g_T1 [(size_t)DDIM * DDIM];     // T1 = (cs⊙dir) @ lora_A^T
__device__ f16 g_QT [(size_t)DDIM * DDIM];     // QT = T1 @ lora_B^T
__device__ float g_cs[DDIM];

// ---------------------------------------------------------------------------
// PTX helpers — standard sm_80 features only
// ---------------------------------------------------------------------------
__device__ __forceinline__ uint32_t smem_u32(const void* p) {
    uint32_t a;
    asm("{ .reg .u64 t; cvta.to.shared.u64 t, %1; cvt.u32.u64 %0, t; }" : "=r"(a) : "l"(p));
    return a;
}
__device__ __forceinline__ void cp_async16(uint32_t dst, const void* src) {
    asm volatile("cp.async.cg.shared.global [%0], [%1], 16;" :: "r"(dst), "l"(src));
}
__device__ __forceinline__ void cp_commit() { asm volatile("cp.async.commit_group;" ::: "memory"); }
template <int N>
__device__ __forceinline__ void cp_wait() { asm volatile("cp.async.wait_group %0;" :: "n"(N) : "memory"); }

#define LDSM_X4(r0, r1, r2, r3, addr) \
    asm volatile("ldmatrix.sync.aligned.m8n8.x4.shared.b16 {%0,%1,%2,%3}, [%4];" \
        : "=r"(r0), "=r"(r1), "=r"(r2), "=r"(r3) : "r"(addr))

__device__ __forceinline__ void mma_f16(float* c, const uint32_t* a, const uint32_t* b) {
    asm volatile(
        "mma.sync.aligned.m16n8k16.row.col.f32.f16.f16.f32 "
        "{%0,%1,%2,%3}, {%4,%5,%6,%7}, {%8,%9}, {%0,%1,%2,%3};"
        : "+f"(c[0]), "+f"(c[1]), "+f"(c[2]), "+f"(c[3])
        : "r"(a[0]), "r"(a[1]), "r"(a[2]), "r"(a[3]), "r"(b[0]), "r"(b[1]));
}

// ---------------------------------------------------------------------------
// Prep 1: cs[o] = ||magnitude|| * SCALING / max(||direction[o,:]||, eps)
// ---------------------------------------------------------------------------
__global__ void magcol_kernel(const float* __restrict__ magnitude,
                              const float* __restrict__ direction) {
    int o = blockIdx.x;
    const float* row = direction + (size_t)o * DDIM;
    float sm = 0.0f, sd = 0.0f;
    for (int i = threadIdx.x; i < DDIM; i += 256) {
        float a = magnitude[i];  sm += a * a;
        float b = row[i];        sd += b * b;
    }
    __shared__ float rm[256], rd[256];
    rm[threadIdx.x] = sm; rd[threadIdx.x] = sd;
    __syncthreads();
    for (int off = 128; off > 0; off >>= 1) {
        if (threadIdx.x < off) {
            rm[threadIdx.x] += rm[threadIdx.x + off];
            rd[threadIdx.x] += rd[threadIdx.x + off];
        }
        __syncthreads();
    }
    if (threadIdx.x == 0)
        g_cs[o] = sqrtf(rm[0]) * SCALING_F / fmaxf(sqrtf(rd[0]), EPS_F);
}

// ---------------------------------------------------------------------------
// Prep 2: fused fp32 -> fp16 conversions (8 elems/thread, 16B stores)
// ---------------------------------------------------------------------------
__device__ __forceinline__ void cvt8(const float* __restrict__ in, f16* __restrict__ out,
                                     int i, float s) {
    float4 a = ((const float4*)in)[i * 2];
    float4 b = ((const float4*)in)[i * 2 + 1];
    __half2 h0 = __floats2half2_rn(a.x * s, a.y * s);
    __half2 h1 = __floats2half2_rn(a.z * s, a.w * s);
    __half2 h2 = __floats2half2_rn(b.x * s, b.y * s);
    __half2 h3 = __floats2half2_rn(b.z * s, b.w * s);
    uint4 v; v.x = *(uint32_t*)&h0; v.y = *(uint32_t*)&h1;
    v.z = *(uint32_t*)&h2; v.w = *(uint32_t*)&h3;
    ((uint4*)out)[i] = v;
}

#define NX8 ((NTOK * DDIM) / 8)
#define ND8 ((DDIM * DDIM) / 8)
#define BX  (NX8 / 256)
#define BD  (ND8 / 256)

__global__ void fused_prep(const float* __restrict__ x,
                           const float* __restrict__ lA,
                           const float* __restrict__ lB,
                           const float* __restrict__ dir) {
    int b = blockIdx.x;
    if (b < BX) {
        cvt8(x, g_x16, b * 256 + threadIdx.x, 1.0f);
    } else if (b < BX + BD) {
        cvt8(lA, g_lA, (b - BX) * 256 + threadIdx.x, 1.0f);
    } else if (b < BX + 2 * BD) {
        cvt8(lB, g_lB, (b - BX - BD) * 256 + threadIdx.x, 1.0f);
    } else {
        int i = (b - BX - 2 * BD) * 256 + threadIdx.x;
        int row = (i * 8) / DDIM;        // 8 | DDIM -> row constant across the 8
        cvt8(dir, g_ds, i, g_cs[row]);
    }
}

// ---------------------------------------------------------------------------
// fp16 GEMM (single pass), OCCUPANCY 2: C = A[M,K] * B[N,K]^T, K = 2048.
// CTA tile 128x128, warp tile 64x32, BK=64, S=3 stages (32 KB each = 96 KB
// -> 2 CTAs/SM), single-buffered fragments (keeps regs <= 128), SW128 XOR
// swizzle. EPI=0: fp32 out.  EPI=1: fp16 out.
// ---------------------------------------------------------------------------
template <int EPI>
__global__ __launch_bounds__(256, 2)
void gemm_f16(const f16* __restrict__ A_g, const f16* __restrict__ B_g,
              float* __restrict__ Cf, f16* __restrict__ Ch)
{
    extern __shared__ __align__(128) char smem[];
    const uint32_t sb = smem_u32(smem);

    constexpr int K = KDIM, BK = 64, NC = K / BK, S = 3;
    constexpr uint32_t TILE = 128 * 128;       // 16 KB
    constexpr uint32_t STAGE = 2 * TILE;       // 32 KB

    const int tid = threadIdx.x;
    const int m0 = blockIdx.y * 128;
    const int n0 = blockIdx.x * 128;
    const int ldc = gridDim.x * 128;
    const int wid = tid >> 5, lane = tid & 31;
    const int wm = (wid >> 2) * 64;
    const int wn = (wid & 3) * 32;

    const int lrow = tid >> 3;        // 0..31
    const int lg   = tid & 7;         // 16B group in 128B row
    const f16* gpA = A_g + (size_t)m0 * K;
    const f16* gpB = B_g + (size_t)n0 * K;

    auto load_stage = [&](int slot, int c) {
        const uint32_t base = sb + (uint32_t)slot * STAGE;
        const int k0 = c * BK + lg * 8;
        #pragma unroll
        for (int t = 0; t < 2; t++) {
            const f16* bp = (t == 0) ? gpA : gpB;
            #pragma unroll
            for (int j = 0; j < 4; j++) {
                const int row = lrow + 32 * j;
                uint32_t off = (uint32_t)row * 128 + (uint32_t)lg * 16;
                off ^= ((uint32_t)row & 7) << 4;
                cp_async16(base + (uint32_t)t * TILE + off, bp + (size_t)row * K + k0);
            }
        }
        cp_commit();
    };

    float acc[4][4][4];
    #pragma unroll
    for (int a = 0; a < 4; a++)
        #pragma unroll
        for (int b = 0; b < 4; b++)
            #pragma unroll
            for (int q = 0; q < 4; q++) acc[a][b][q] = 0.0f;

    load_stage(0, 0);
    load_stage(1, 1);

    // ldmatrix lane components
    const int a_row_l = lane & 15;
    const int a_kb_l  = (lane >> 4) * 16;
    const int b_n_l   = (lane & 7) + ((lane >> 4) << 3);
    const int b_kb_l  = ((lane >> 3) & 1) * 16;

    for (int c = 0; c < NC; c++) {
        if (c + 1 < NC) cp_wait<1>(); else cp_wait<0>();
        __syncthreads();
        if (c + 2 < NC) load_stage((c + 2) % S, c + 2);

        const uint32_t stg = sb + (uint32_t)(c % S) * STAGE;
        const uint32_t As = stg, Bs = stg + TILE;

        #pragma unroll
        for (int s = 0; s < 4; s++) {     // 4 k16 steps per 64-chunk
            const int kb = s * 32;
            uint32_t ah[4][4], bh[4][2];   // single-buffered (regs <= 128)
            #pragma unroll
            for (int mi = 0; mi < 4; mi++) {
                const int row = wm + mi * 16 + a_row_l;
                const uint32_t off = (uint32_t)row * 128
                    + (((uint32_t)(kb + a_kb_l)) ^ (((uint32_t)row & 7) << 4));
                LDSM_X4(ah[mi][0], ah[mi][1], ah[mi][2], ah[mi][3], As + off);
            }
            #pragma unroll
            for (int nj2 = 0; nj2 < 2; nj2++) {
                const int nr = wn + nj2 * 16 + b_n_l;
                const uint32_t off = (uint32_t)nr * 128
                    + (((uint32_t)(kb + b_kb_l)) ^ (((uint32_t)nr & 7) << 4));
                LDSM_X4(bh[2*nj2][0], bh[2*nj2][1], bh[2*nj2+1][0], bh[2*nj2+1][1],
                        Bs + off);
            }
            #pragma unroll
            for (int mi = 0; mi < 4; mi++)
                #pragma unroll
                for (int nj = 0; nj < 4; nj++)
                    mma_f16(acc[mi][nj], ah[mi], bh[nj]);
        }
    }

    // ---------------- epilogue ----------------
    const int g  = lane >> 2;
    const int t4 = lane & 3;
    #pragma unroll
    for (int mi = 0; mi < 4; mi++) {
        const int r0 = m0 + wm + mi * 16 + g;
        const int r1 = r0 + 8;
        #pragma unroll
        for (int nj = 0; nj < 4; nj++) {
            const int col = n0 + wn + nj * 8 + t4 * 2;
            float c0 = acc[mi][nj][0], c1 = acc[mi][nj][1];
            float c2 = acc[mi][nj][2], c3 = acc[mi][nj][3];
            if (EPI == 0) {
                float2 v0; v0.x = c0; v0.y = c1;
                float2 v1; v1.x = c2; v1.y = c3;
                *(float2*)(Cf + (size_t)r0 * ldc + col) = v0;
                *(float2*)(Cf + (size_t)r1 * ldc + col) = v1;
            } else {
                __half2 h0 = __floats2half2_rn(c0, c1);
                __half2 h1 = __floats2half2_rn(c2, c3);
                *(__half2*)(Ch + (size_t)r0 * ldc + col) = h0;
                *(__half2*)(Ch + (size_t)r1 * ldc + col) = h1;
            }
        }
    }
}

// ---------------------------------------------------------------------------
// Launch: magcol(1) -> fused_prep(2) -> gemm1(3) -> gemm2(4) -> gemm3(5)
// Chain:  T1 = (cs⊙dir) @ lora_A^T ;  QT = T1 @ lora_B^T ;  out = x @ QT^T
// ---------------------------------------------------------------------------
extern "C" void kernel_launch(void* const* d_in, const int* in_sizes, int n_in,
                              void* d_out, int out_size) {
    const float* x         = (const float*)d_in[0];
    const float* lora_A    = (const float*)d_in[1];
    const float* lora_B    = (const float*)d_in[2];
    const float* magnitude = (const float*)d_in[3];
    const float* direction = (const float*)d_in[4];
    float* out = (float*)d_out;

    f16 *x16, *lA, *lB, *ds, *T1, *QT;
    cudaGetSymbolAddress((void**)&x16, g_x16);
    cudaGetSymbolAddress((void**)&lA, g_lA);
    cudaGetSymbolAddress((void**)&lB, g_lB);
    cudaGetSymbolAddress((void**)&ds, g_ds);
    cudaGetSymbolAddress((void**)&T1, g_T1);
    cudaGetSymbolAddress((void**)&QT, g_QT);

    constexpr int SM = 3 * 2 * 128 * 128;   // 98304 bytes (2 CTAs/SM fit 192KB)
    cudaFuncSetAttribute(gemm_f16<0>, cudaFuncAttributeMaxDynamicSharedMemorySize, SM);
    cudaFuncSetAttribute(gemm_f16<1>, cudaFuncAttributeMaxDynamicSharedMemorySize, SM);

    // 1: norms (must precede prep: dir is pre-scaled by cs)
    magcol_kernel<<<DDIM, 256>>>(magnitude, direction);
    // 2: fused conversions
    fused_prep<<<BX + 3 * BD, 256>>>(x, lora_A, lora_B, direction);

    dim3 gs(DDIM / 128, DDIM / 128);   // 256 CTAs (one wave at occ 2)
    dim3 gb(DDIM / 128, NTOK / 128);   // 1024 CTAs

    // 3: T1 = (cs⊙dir) @ lora_A^T   (fp16 out)
    gemm_f16<1><<<gs, 256, SM>>>(ds, lA, nullptr, T1);
    // 4: QT = T1 @ lora_B^T          (fp16 out)
    gemm_f16<1><<<gs, 256, SM>>>(T1, lB, nullptr, QT);
    // 5: out = x @ QT^T              (fp32 out)
    gemm_f16<0><<<gb, 256, SM>>>(x16, QT, out, nullptr);
}

// round 17
// speedup vs baseline: 1.3757x; 1.0288x over previous
#include <cuda_runtime.h>
#include <cuda_fp16.h>
#include <cstdint>
#include <math.h>

typedef __half f16;

#define NTOK 8192
#define DDIM 2048
#define KDIM 2048
#define SCALING_F (16.0f / 2048.0f)
#define EPS_F 1e-12f

// ---------------------------------------------------------------------------
// Static device scratch
// ---------------------------------------------------------------------------
__device__ f16 g_x16[(size_t)NTOK * DDIM];     // x
__device__ f16 g_lA [(size_t)DDIM * DDIM];     // lora_A
__device__ f16 g_lB [(size_t)DDIM * DDIM];     // lora_B
__device__ f16 g_ds [(size_t)DDIM * DDIM];     // cs ⊙ direction
__device__ f16 g_T1 [(size_t)DDIM * DDIM];     // T1 = (cs⊙dir) @ lora_A^T
__device__ f16 g_QT [(size_t)DDIM * DDIM];     // QT = T1 @ lora_B^T
__device__ float g_cs[DDIM];

// ---------------------------------------------------------------------------
// PTX helpers — standard sm_80 features only
// ---------------------------------------------------------------------------
__device__ __forceinline__ uint32_t smem_u32(const void* p) {
    uint32_t a;
    asm("{ .reg .u64 t; cvta.to.shared.u64 t, %1; cvt.u32.u64 %0, t; }" : "=r"(a) : "l"(p));
    return a;
}
__device__ __forceinline__ void cp_async16(uint32_t dst, const void* src) {
    asm volatile("cp.async.cg.shared.global [%0], [%1], 16;" :: "r"(dst), "l"(src));
}
__device__ __forceinline__ void cp_commit() { asm volatile("cp.async.commit_group;" ::: "memory"); }
template <int N>
__device__ __forceinline__ void cp_wait() { asm volatile("cp.async.wait_group %0;" :: "n"(N) : "memory"); }

#define LDSM_X4(r0, r1, r2, r3, addr) \
    asm volatile("ldmatrix.sync.aligned.m8n8.x4.shared.b16 {%0,%1,%2,%3}, [%4];" \
        : "=r"(r0), "=r"(r1), "=r"(r2), "=r"(r3) : "r"(addr))

__device__ __forceinline__ void mma_f16(float* c, const uint32_t* a, const uint32_t* b) {
    asm volatile(
        "mma.sync.aligned.m16n8k16.row.col.f32.f16.f16.f32 "
        "{%0,%1,%2,%3}, {%4,%5,%6,%7}, {%8,%9}, {%0,%1,%2,%3};"
        : "+f"(c[0]), "+f"(c[1]), "+f"(c[2]), "+f"(c[3])
        : "r"(a[0]), "r"(a[1]), "r"(a[2]), "r"(a[3]), "r"(b[0]), "r"(b[1]));
}

// ---------------------------------------------------------------------------
// Conversion primitive: 8 fp32 -> 8 fp16, 16B store
// ---------------------------------------------------------------------------
__device__ __forceinline__ void cvt8(const float* __restrict__ in, f16* __restrict__ out,
                                     int i, float s) {
    float4 a = ((const float4*)in)[i * 2];
    float4 b = ((const float4*)in)[i * 2 + 1];
    __half2 h0 = __floats2half2_rn(a.x * s, a.y * s);
    __half2 h1 = __floats2half2_rn(a.z * s, a.w * s);
    __half2 h2 = __floats2half2_rn(b.x * s, b.y * s);
    __half2 h3 = __floats2half2_rn(b.z * s, b.w * s);
    uint4 v; v.x = *(uint32_t*)&h0; v.y = *(uint32_t*)&h1;
    v.z = *(uint32_t*)&h2; v.w = *(uint32_t*)&h3;
    ((uint4*)out)[i] = v;
}

// ---------------------------------------------------------------------------
// Prep 1: cs[o] = ||magnitude|| * SCALING / max(||direction[o,:]||, eps)
// ---------------------------------------------------------------------------
__global__ void magcol_kernel(const float* __restrict__ magnitude,
                              const float* __restrict__ direction) {
    int o = blockIdx.x;
    const float* row = direction + (size_t)o * DDIM;
    float sm = 0.0f, sd = 0.0f;
    for (int i = threadIdx.x; i < DDIM; i += 256) {
        float a = magnitude[i];  sm += a * a;
        float b = row[i];        sd += b * b;
    }
    __shared__ float rm[256], rd[256];
    rm[threadIdx.x] = sm; rd[threadIdx.x] = sd;
    __syncthreads();
    for (int off = 128; off > 0; off >>= 1) {
        if (threadIdx.x < off) {
            rm[threadIdx.x] += rm[threadIdx.x + off];
            rd[threadIdx.x] += rd[threadIdx.x + off];
        }
        __syncthreads();
    }
    if (threadIdx.x == 0)
        g_cs[o] = sqrtf(rm[0]) * SCALING_F / fmaxf(sqrtf(rd[0]), EPS_F);
}

// ---------------------------------------------------------------------------
// Prep 2: weight conversions only (x converted inside gemm1's mainloop)
// ---------------------------------------------------------------------------
#define NX8 ((NTOK * DDIM) / 8)
#define ND8 ((DDIM * DDIM) / 8)
#define XU  (NX8 / 256)            // 8192 x-units (one unit = 256 thr x 8 elems)
#define BD  (ND8 / 256)

__global__ void weights_prep(const float* __restrict__ lA,
                             const float* __restrict__ lB,
                             const float* __restrict__ dir) {
    int b = blockIdx.x;
    if (b < BD) {
        cvt8(lA, g_lA, b * 256 + threadIdx.x, 1.0f);
    } else if (b < 2 * BD) {
        cvt8(lB, g_lB, (b - BD) * 256 + threadIdx.x, 1.0f);
    } else {
        int i = (b - 2 * BD) * 256 + threadIdx.x;
        int row = (i * 8) / DDIM;        // 8 | DDIM -> row constant across the 8
        cvt8(dir, g_ds, i, g_cs[row]);
    }
}

// ---------------------------------------------------------------------------
// fp16 GEMM (single pass), OCCUPANCY 2: C = A[M,K] * B[N,K]^T, K = 2048.
// CTA tile 128x128, warp tile 64x32, BK=64, S=3 stages (96 KB -> 2 CTAs/SM),
// single-buffered fragments.  XCVT=1: each mainloop iteration additionally
// converts one x-unit (8 fp32->fp16 per thread) — with 256 CTAs x 32 chunks
// this covers all 8192 units, hiding the x prep entirely inside gemm1.
// EPI=0: fp32 out.  EPI=1: fp16 out.
// ---------------------------------------------------------------------------
template <int EPI, int XCVT>
__global__ __launch_bounds__(256, 2)
void gemm_f16(const f16* __restrict__ A_g, const f16* __restrict__ B_g,
              float* __restrict__ Cf, f16* __restrict__ Ch,
              const float* __restrict__ xsrc)
{
    extern __shared__ __align__(128) char smem[];
    const uint32_t sb = smem_u32(smem);

    constexpr int K = KDIM, BK = 64, NC = K / BK, S = 3;
    constexpr uint32_t TILE = 128 * 128;       // 16 KB
    constexpr uint32_t STAGE = 2 * TILE;       // 32 KB

    const int tid = threadIdx.x;
    const int m0 = blockIdx.y * 128;
    const int n0 = blockIdx.x * 128;
    const int ldc = gridDim.x * 128;
    const int wid = tid >> 5, lane = tid & 31;
    const int wm = (wid >> 2) * 64;
    const int wn = (wid & 3) * 32;

    // x-conversion base unit for this CTA (XCVT only)
    const int xu0 = XCVT ? (blockIdx.y * gridDim.x + blockIdx.x) * NC : 0;

    const int lrow = tid >> 3;        // 0..31
    const int lg   = tid & 7;         // 16B group in 128B row
    const f16* gpA = A_g + (size_t)m0 * K;
    const f16* gpB = B_g + (size_t)n0 * K;

    auto load_stage = [&](int slot, int c) {
        const uint32_t base = sb + (uint32_t)slot * STAGE;
        const int k0 = c * BK + lg * 8;
        #pragma unroll
        for (int t = 0; t < 2; t++) {
            const f16* bp = (t == 0) ? gpA : gpB;
            #pragma unroll
            for (int j = 0; j < 4; j++) {
                const int row = lrow + 32 * j;
                uint32_t off = (uint32_t)row * 128 + (uint32_t)lg * 16;
                off ^= ((uint32_t)row & 7) << 4;
                cp_async16(base + (uint32_t)t * TILE + off, bp + (size_t)row * K + k0);
            }
        }
        cp_commit();
    };

    float acc[4][4][4];
    #pragma unroll
    for (int a = 0; a < 4; a++)
        #pragma unroll
        for (int b = 0; b < 4; b++)
            #pragma unroll
            for (int q = 0; q < 4; q++) acc[a][b][q] = 0.0f;

    load_stage(0, 0);
    load_stage(1, 1);

    // ldmatrix lane components
    const int a_row_l = lane & 15;
    const int a_kb_l  = (lane >> 4) * 16;
    const int b_n_l   = (lane & 7) + ((lane >> 4) << 3);
    const int b_kb_l  = ((lane >> 3) & 1) * 16;

    for (int c = 0; c < NC; c++) {
        if (c + 1 < NC) cp_wait<1>(); else cp_wait<0>();
        __syncthreads();
        if (c + 2 < NC) load_stage((c + 2) % S, c + 2);

        // side job: convert one x unit this iteration (independent dataflow;
        // latency absorbed by the 16 warps/SM while tensor pipe churns)
        if (XCVT)
            cvt8(xsrc, g_x16, (xu0 + c) * 256 + tid, 1.0f);

        const uint32_t stg = sb + (uint32_t)(c % S) * STAGE;
        const uint32_t As = stg, Bs = stg + TILE;

        #pragma unroll
        for (int s = 0; s < 4; s++) {     // 4 k16 steps per 64-chunk
            const int kb = s * 32;
            uint32_t ah[4][4], bh[4][2];   // single-buffered (regs <= 128)
            #pragma unroll
            for (int mi = 0; mi < 4; mi++) {
                const int row = wm + mi * 16 + a_row_l;
                const uint32_t off = (uint32_t)row * 128
                    + (((uint32_t)(kb + a_kb_l)) ^ (((uint32_t)row & 7) << 4));
                LDSM_X4(ah[mi][0], ah[mi][1], ah[mi][2], ah[mi][3], As + off);
            }
            #pragma unroll
            for (int nj2 = 0; nj2 < 2; nj2++) {
                const int nr = wn + nj2 * 16 + b_n_l;
                const uint32_t off = (uint32_t)nr * 128
                    + (((uint32_t)(kb + b_kb_l)) ^ (((uint32_t)nr & 7) << 4));
                LDSM_X4(bh[2*nj2][0], bh[2*nj2][1], bh[2*nj2+1][0], bh[2*nj2+1][1],
                        Bs + off);
            }
            #pragma unroll
            for (int mi = 0; mi < 4; mi++)
                #pragma unroll
                for (int nj = 0; nj < 4; nj++)
                    mma_f16(acc[mi][nj], ah[mi], bh[nj]);
        }
    }

    // ---------------- epilogue ----------------
    const int g  = lane >> 2;
    const int t4 = lane & 3;
    #pragma unroll
    for (int mi = 0; mi < 4; mi++) {
        const int r0 = m0 + wm + mi * 16 + g;
        const int r1 = r0 + 8;
        #pragma unroll
        for (int nj = 0; nj < 4; nj++) {
            const int col = n0 + wn + nj * 8 + t4 * 2;
            float c0 = acc[mi][nj][0], c1 = acc[mi][nj][1];
            float c2 = acc[mi][nj][2], c3 = acc[mi][nj][3];
            if (EPI == 0) {
                float2 v0; v0.x = c0; v0.y = c1;
                float2 v1; v1.x = c2; v1.y = c3;
                *(float2*)(Cf + (size_t)r0 * ldc + col) = v0;
                *(float2*)(Cf + (size_t)r1 * ldc + col) = v1;
            } else {
                __half2 h0 = __floats2half2_rn(c0, c1);
                __half2 h1 = __floats2half2_rn(c2, c3);
                *(__half2*)(Ch + (size_t)r0 * ldc + col) = h0;
                *(__half2*)(Ch + (size_t)r1 * ldc + col) = h1;
            }
        }
    }
}

// ---------------------------------------------------------------------------
// Launch: magcol(1) -> weights_prep(2) -> gemm1(+x convert)(3) -> gemm2(4)
//         -> gemm3(5)
// Chain:  T1 = (cs⊙dir) @ lora_A^T ;  QT = T1 @ lora_B^T ;  out = x @ QT^T
// ---------------------------------------------------------------------------
extern "C" void kernel_launch(void* const* d_in, const int* in_sizes, int n_in,
                              void* d_out, int out_size) {
    const float* x         = (const float*)d_in[0];
    const float* lora_A    = (const float*)d_in[1];
    const float* lora_B    = (const float*)d_in[2];
    const float* magnitude = (const float*)d_in[3];
    const float* direction = (const float*)d_in[4];
    float* out = (float*)d_out;

    f16 *x16, *lA, *lB, *ds, *T1, *QT;
    cudaGetSymbolAddress((void**)&x16, g_x16);
    cudaGetSymbolAddress((void**)&lA, g_lA);
    cudaGetSymbolAddress((void**)&lB, g_lB);
    cudaGetSymbolAddress((void**)&ds, g_ds);
    cudaGetSymbolAddress((void**)&T1, g_T1);
    cudaGetSymbolAddress((void**)&QT, g_QT);

    constexpr int SM = 3 * 2 * 128 * 128;   // 98304 bytes (2 CTAs/SM)
    cudaFuncSetAttribute((const void*)gemm_f16<0, 0>,
                         cudaFuncAttributeMaxDynamicSharedMemorySize, SM);
    cudaFuncSetAttribute((const void*)gemm_f16<1, 0>,
                         cudaFuncAttributeMaxDynamicSharedMemorySize, SM);
    cudaFuncSetAttribute((const void*)gemm_f16<1, 1>,
                         cudaFuncAttributeMaxDynamicSharedMemorySize, SM);

    // 1: norms (must precede prep: dir is pre-scaled by cs)
    magcol_kernel<<<DDIM, 256>>>(magnitude, direction);
    // 2: weight conversions (x handled inside gemm1)
    weights_prep<<<3 * BD, 256>>>(lora_A, lora_B, direction);

    dim3 gs(DDIM / 128, DDIM / 128);   // 256 CTAs (one wave at occ 2)
    dim3 gb(DDIM / 128, NTOK / 128);   // 1024 CTAs

    // 3: T1 = (cs⊙dir) @ lora_A^T   (fp16 out) + x fp32->fp16 side-convert
    //    (256 CTAs x 32 chunks == 8192 units == all of x)
    gemm_f16<1, 1><<<gs, 256, SM>>>(ds, lA, nullptr, T1, x);
    // 4: QT = T1 @ lora_B^T          (fp16 out)
    gemm_f16<1, 0><<<gs, 256, SM>>>(T1, lB, nullptr, QT, nullptr);
    // 5: out = x @ QT^T              (fp32 out)
    gemm_f16<0, 0><<<gb, 256, SM>>>(x16, QT, out, nullptr, nullptr);
}